// round 16
// baseline (speedup 1.0000x reference)
#include <cuda_runtime.h>
#include <cstdint>

#define H96   96
#define HW    9216          // 96*96
#define CIN   256
#define C8C   32
#define NB    16
#define KK    11
#define KTOT  2816          // CIN*KK
#define MQK   64            // 32 q + 32 k fused
#define VM    256           // v output channels
#define ATT_N 192

#define VROWS 32
#define VPAD  136
#define VBUF  (VROWS * VPAD)                    // floats per (As|Bs) buffer
#define VSMEM_BYTES (4 * VBUF * 2 * 2)          // 2 arrays x 2 buffers = 69632 B

typedef unsigned long long u64;

// ---- packed f32x2 helpers (FFMA2) ----
__device__ __forceinline__ u64 pack2(float x) {
    unsigned u = __float_as_uint(x);
    u64 r; asm("mov.b64 %0, {%1, %1};" : "=l"(r) : "r"(u)); return r;
}
__device__ __forceinline__ void fma2(u64& c, u64 a, u64 b) {
    asm("fma.rn.f32x2 %0, %1, %2, %0;" : "+l"(c) : "l"(a), "l"(b));
}
__device__ __forceinline__ float2 unpack2(u64 v) {
    unsigned lo, hi;
    asm("mov.b64 {%0, %1}, %2;" : "=r"(lo), "=r"(hi) : "l"(v));
    return make_float2(__uint_as_float(lo), __uint_as_float(hi));
}
__device__ __forceinline__ float to_tf32(float x) {
    unsigned t; asm("cvt.rna.tf32.f32 %0, %1;" : "=r"(t) : "f"(x));
    return __uint_as_float(t);
}

// ---------------- scratch ----------------
__device__ float g_wqkv[KTOT * MQK];          // q/k vertical weights, K-major fp32
__device__ float g_wqkh[KTOT * MQK];          // q/k horizontal
__device__ float g_wvv [KTOT * VM];           // v vertical weights, K-major tf32
__device__ float g_wvh2[KTOT * VM];           // v horizontal
__device__ float g_xt  [NB * CIN * HW];       // x pre-rounded to tf32
__device__ float g_qh [NB * C8C * HW];
__device__ float g_kh [NB * C8C * HW];
__device__ float g_vh [NB * CIN * HW];
__device__ float g_qw [NB * C8C * HW];
__device__ float g_kw [NB * C8C * HW];
__device__ float g_vw [NB * CIN * HW];
__device__ float g_qhT[NB * C8C * HW];
__device__ float g_khT[NB * C8C * HW];
__device__ float g_vhT[NB * CIN * HW];
__device__ float g_att[(size_t)NB * HW * ATT_N];
__device__ float g_oh [NB * CIN * HW];
__device__ float g_ow [NB * CIN * HW];

// ---------------- weight / x repack ----------------
__global__ void prep_qk(const float* __restrict__ wq, const float* __restrict__ wk,
                        float* __restrict__ Wt)
{
    int idx = blockIdx.x * 256 + threadIdx.x;
    if (idx >= KTOT * MQK) return;
    int k  = idx / MQK;
    int co = idx - k * MQK;
    int ci = k / KK;
    int dk = k - ci * KK;
    float v = (co < C8C) ? wq[(co * CIN + ci) * KK + dk]
                         : wk[((co - C8C) * CIN + ci) * KK + dk];
    Wt[idx] = v;
}
__global__ void prep_v(const float* __restrict__ wv, float* __restrict__ Wt)
{
    int idx = blockIdx.x * 256 + threadIdx.x;
    if (idx >= KTOT * VM) return;
    int k  = idx / VM;
    int co = idx - k * VM;
    int ci = k / KK;
    int dk = k - ci * KK;
    Wt[idx] = to_tf32(wv[(co * CIN + ci) * KK + dk]);
}
__global__ void prep_x(const float* __restrict__ x, float* __restrict__ xt)
{
    size_t i = (size_t)blockIdx.x * 256 + threadIdx.x;
    if (i < (size_t)NB * CIN * HW) xt[i] = to_tf32(x[i]);
}

// ---------------- q/k conv GEMM (fp32 FFMA2, M=64) ----------------
template<int DIR>
__global__ void __launch_bounds__(128) qk_conv(
    const float* __restrict__ x, const float* __restrict__ Wt,
    const float* __restrict__ bq, const float* __restrict__ bk,
    float* __restrict__ oq, float* __restrict__ okk)
{
    const int b  = blockIdx.z;
    const int n0 = blockIdx.x * 128;
    const float* xb = x + (size_t)b * CIN * HW;

    const int tid = threadIdx.x;
    const int tn  = tid & 15;
    const int tm  = tid >> 4;
    const int n   = n0 + tid;
    const int hq  = n / H96;
    const int wq_ = n - hq * H96;

    __shared__ __align__(16) float As[16][64];
    __shared__ __align__(16) float Bs[16][128];

    u64 acc[8][4];
#pragma unroll
    for (int i = 0; i < 8; i++)
#pragma unroll
        for (int j = 0; j < 4; j++) acc[i][j] = 0ull;

    const int arow = tid >> 6;
    const int acol = tid & 63;

    float aReg[8];
    float bReg[16];

#pragma unroll
    for (int i = 0; i < 8; i++)
        aReg[i] = Wt[(i * 2 + arow) * MQK + acol];
#pragma unroll
    for (int i = 0; i < 16; i++) {
        int ci = i / KK;
        int dk = i - ci * KK;
        float v = 0.f;
        if (DIR == 0) {
            int hp = hq + dk - 5;
            if ((unsigned)hp < (unsigned)H96) v = xb[ci * HW + hp * H96 + wq_];
        } else {
            int wp = wq_ + dk - 5;
            if ((unsigned)wp < (unsigned)H96) v = xb[ci * HW + hq * H96 + wp];
        }
        bReg[i] = v;
    }

    for (int k0 = 0; k0 < KTOT; k0 += 16) {
#pragma unroll
        for (int i = 0; i < 8; i++)
            As[i * 2 + arow][acol] = aReg[i];
#pragma unroll
        for (int i = 0; i < 16; i++)
            Bs[i][tid] = bReg[i];
        __syncthreads();

        if (k0 + 16 < KTOT) {
            const int kn = k0 + 16;
#pragma unroll
            for (int i = 0; i < 8; i++)
                aReg[i] = Wt[(kn + i * 2 + arow) * MQK + acol];
#pragma unroll
            for (int i = 0; i < 16; i++) {
                int k  = kn + i;
                int ci = k / KK;
                int dk = k - ci * KK;
                float v = 0.f;
                if (DIR == 0) {
                    int hp = hq + dk - 5;
                    if ((unsigned)hp < (unsigned)H96) v = xb[ci * HW + hp * H96 + wq_];
                } else {
                    int wp = wq_ + dk - 5;
                    if ((unsigned)wp < (unsigned)H96) v = xb[ci * HW + hq * H96 + wp];
                }
                bReg[i] = v;
            }
        }

#pragma unroll
        for (int kk = 0; kk < 16; kk++) {
            const float4 a0 = *reinterpret_cast<const float4*>(&As[kk][tm * 8]);
            const float4 a1 = *reinterpret_cast<const float4*>(&As[kk][tm * 8 + 4]);
            u64 ap[8];
            ap[0] = pack2(a0.x); ap[1] = pack2(a0.y); ap[2] = pack2(a0.z); ap[3] = pack2(a0.w);
            ap[4] = pack2(a1.x); ap[5] = pack2(a1.y); ap[6] = pack2(a1.z); ap[7] = pack2(a1.w);
            const u64* b0 = reinterpret_cast<const u64*>(&Bs[kk][tn * 4]);
            const u64* b1 = reinterpret_cast<const u64*>(&Bs[kk][64 + tn * 4]);
            u64 bp[4];
            bp[0] = b0[0]; bp[1] = b0[1]; bp[2] = b1[0]; bp[3] = b1[1];
#pragma unroll
            for (int mi = 0; mi < 8; mi++)
#pragma unroll
                for (int nj = 0; nj < 4; nj++)
                    fma2(acc[mi][nj], ap[mi], bp[nj]);
        }
        __syncthreads();
    }

#pragma unroll
    for (int mi = 0; mi < 8; mi++) {
        int co = tm * 8 + mi;
        float bias; float* dst;
        if (co < C8C) { bias = bq[co];       dst = oq  + (size_t)(b * C8C + co) * HW; }
        else          { bias = bk[co - C8C]; dst = okk + (size_t)(b * C8C + co - C8C) * HW; }
        float2 p0 = unpack2(acc[mi][0]);
        float2 p1 = unpack2(acc[mi][1]);
        float2 p2 = unpack2(acc[mi][2]);
        float2 p3 = unpack2(acc[mi][3]);
        float4 v0 = make_float4(p0.x + bias, p0.y + bias, p1.x + bias, p1.y + bias);
        float4 v1 = make_float4(p2.x + bias, p2.y + bias, p3.x + bias, p3.y + bias);
        *reinterpret_cast<float4*>(dst + n0 + tn * 4)      = v0;
        *reinterpret_cast<float4*>(dst + n0 + 64 + tn * 4) = v1;
    }
}

// ---------------- v conv GEMM (tf32 mma.sync, double-buffered, dyn smem) ------
template<int DIR>
__global__ void __launch_bounds__(256) v_conv(
    const float* __restrict__ xt, const float* __restrict__ Wt,
    const float* __restrict__ bv, float* __restrict__ ov)
{
    extern __shared__ float sm[];
    float* Asm = sm;                 // As[pb] at Asm + pb*VBUF
    float* Bsm = sm + 2 * VBUF;      // Bs[pb] at Bsm + pb*VBUF

    const int b  = blockIdx.z;
    const int c0 = blockIdx.y * 128;
    const int n0 = blockIdx.x * 128;
    const float* xb = xt + (size_t)b * CIN * HW;

    const int tid  = threadIdx.x;
    const int warp = tid >> 5, lane = tid & 31;
    const int wm = warp & 1, wn = warp >> 1;
    const int g  = lane >> 2, tg = lane & 3;

    const int ncol  = tid & 127;
    const int rbase = tid >> 7;          // 0/1
    const int n   = n0 + ncol;
    const int hq  = n / H96;
    const int wq_ = n - hq * H96;

    float4 aReg[4];
    float  bReg[16];

    float acc[4][4][4];
#pragma unroll
    for (int a = 0; a < 4; a++)
#pragma unroll
        for (int q = 0; q < 4; q++)
#pragma unroll
            for (int r = 0; r < 4; r++) acc[a][q][r] = 0.f;

#define LOAD_A(KBASE)                                                          \
    {                                                                          \
        _Pragma("unroll")                                                      \
        for (int j = 0; j < 4; j++) {                                          \
            int s  = tid + j * 256;                                            \
            int kr = s >> 5;                                                   \
            int c4 = s & 31;                                                   \
            aReg[j] = *reinterpret_cast<const float4*>(                        \
                Wt + (size_t)((KBASE) + kr) * VM + c0 + c4 * 4);               \
        }                                                                      \
    }
#define STORE_A(PB)                                                            \
    {                                                                          \
        float* dstA = Asm + (PB) * VBUF;                                       \
        _Pragma("unroll")                                                      \
        for (int j = 0; j < 4; j++) {                                          \
            int s  = tid + j * 256;                                            \
            int kr = s >> 5;                                                   \
            int c4 = s & 31;                                                   \
            *reinterpret_cast<float4*>(dstA + kr * VPAD + c4 * 4) = aReg[j];   \
        }                                                                      \
    }
#define LOAD_B(KBASE)                                                          \
    {                                                                          \
        int ks = (KBASE) + rbase;                                              \
        int ci = ks / KK;                                                      \
        int dk = ks - ci * KK;                                                 \
        _Pragma("unroll")                                                      \
        for (int it = 0; it < 16; it++) {                                      \
            float v = 0.f;                                                     \
            if (DIR == 0) {                                                    \
                int hp = hq + dk - 5;                                          \
                if ((unsigned)hp < (unsigned)H96)                              \
                    v = xb[ci * HW + hp * H96 + wq_];                          \
            } else {                                                           \
                int wp = wq_ + dk - 5;                                         \
                if ((unsigned)wp < (unsigned)H96)                              \
                    v = xb[ci * HW + hq * H96 + wp];                           \
            }                                                                  \
            bReg[it] = v;                                                      \
            dk += 2; if (dk >= KK) { dk -= KK; ci++; }                         \
        }                                                                      \
    }
#define STORE_B(PB)                                                            \
    {                                                                          \
        float* dstB = Bsm + (PB) * VBUF;                                       \
        _Pragma("unroll")                                                      \
        for (int it = 0; it < 16; it++)                                        \
            dstB[(2 * it + rbase) * VPAD + ncol] = bReg[it];                   \
    }

    LOAD_A(0); LOAD_B(0);
    STORE_A(0); STORE_B(0);
    __syncthreads();

    int p = 0;
    for (int k0 = 0; k0 < KTOT; k0 += 32) {
        const bool more = (k0 + 32 < KTOT);
        if (more) { LOAD_A(k0 + 32); LOAD_B(k0 + 32); }

        const float* Ap = Asm + p * VBUF;
        const float* Bp = Bsm + p * VBUF;
#pragma unroll
        for (int k8 = 0; k8 < 4; k8++) {
            const int kr = k8 * 8;
            unsigned af[4][4], bf[4][2];
#pragma unroll
            for (int mt = 0; mt < 4; mt++) {
                int mrow = wm * 64 + mt * 16 + g;
                af[mt][0] = __float_as_uint(Ap[(kr + tg) * VPAD + mrow]);
                af[mt][1] = __float_as_uint(Ap[(kr + tg) * VPAD + mrow + 8]);
                af[mt][2] = __float_as_uint(Ap[(kr + tg + 4) * VPAD + mrow]);
                af[mt][3] = __float_as_uint(Ap[(kr + tg + 4) * VPAD + mrow + 8]);
            }
#pragma unroll
            for (int nt = 0; nt < 4; nt++) {
                int nc = wn * 32 + nt * 8 + g;
                bf[nt][0] = __float_as_uint(Bp[(kr + tg) * VPAD + nc]);
                bf[nt][1] = __float_as_uint(Bp[(kr + tg + 4) * VPAD + nc]);
            }
#pragma unroll
            for (int mt = 0; mt < 4; mt++)
#pragma unroll
                for (int nt = 0; nt < 4; nt++)
                    asm volatile(
                        "mma.sync.aligned.m16n8k8.row.col.f32.tf32.tf32.f32 "
                        "{%0,%1,%2,%3}, {%4,%5,%6,%7}, {%8,%9}, {%0,%1,%2,%3};"
                        : "+f"(acc[mt][nt][0]), "+f"(acc[mt][nt][1]),
                          "+f"(acc[mt][nt][2]), "+f"(acc[mt][nt][3])
                        : "r"(af[mt][0]), "r"(af[mt][1]), "r"(af[mt][2]), "r"(af[mt][3]),
                          "r"(bf[nt][0]), "r"(bf[nt][1]));
        }

        if (more) { STORE_A(p ^ 1); STORE_B(p ^ 1); }
        __syncthreads();
        p ^= 1;
    }
#undef LOAD_A
#undef STORE_A
#undef LOAD_B
#undef STORE_B

#pragma unroll
    for (int mt = 0; mt < 4; mt++) {
        int crow0 = c0 + wm * 64 + mt * 16 + g;
        float bias0 = bv[crow0];
        float bias1 = bv[crow0 + 8];
        float* d0 = ov + (size_t)(b * CIN + crow0) * HW;
        float* d1 = ov + (size_t)(b * CIN + crow0 + 8) * HW;
#pragma unroll
        for (int nt = 0; nt < 4; nt++) {
            int nn = n0 + wn * 32 + nt * 8 + 2 * tg;
            d0[nn]     = acc[mt][nt][0] + bias0;
            d0[nn + 1] = acc[mt][nt][1] + bias0;
            d1[nn]     = acc[mt][nt][2] + bias1;
            d1[nn + 1] = acc[mt][nt][3] + bias1;
        }
    }
}

// ---------------- (h,w)-plane transpose ----------------
__global__ void transpose_hw(const float* __restrict__ in, float* __restrict__ out)
{
    __shared__ float t[32][33];
    const int p  = blockIdx.z;
    const int h0 = blockIdx.y * 32, w0 = blockIdx.x * 32;
    const float* ip = in  + (size_t)p * HW;
    float*       op = out + (size_t)p * HW;
#pragma unroll
    for (int i = threadIdx.y; i < 32; i += 8)
        t[i][threadIdx.x] = ip[(h0 + i) * H96 + w0 + threadIdx.x];
    __syncthreads();
#pragma unroll
    for (int i = threadIdx.y; i < 32; i += 8)
        op[(w0 + i) * H96 + h0 + threadIdx.x] = t[threadIdx.x][i];
}

// ---------------- logits ----------------
template<bool MASK>
__global__ void __launch_bounds__(256) logits_kernel(
    const float* __restrict__ Qp, const float* __restrict__ Kp, float* __restrict__ att)
{
    const int bs = blockIdx.x;
    const int b  = bs / H96;
    const int s  = bs - b * H96;
    __shared__ float Qs[C8C][H96];
    __shared__ float Ks[C8C][H96];
    const float* qbase = Qp + (size_t)b * C8C * HW + s * H96;
    const float* kbase = Kp + (size_t)b * C8C * HW + s * H96;
    for (int e = threadIdx.x; e < C8C * H96; e += 256) {
        int c  = e / H96;
        int pp = e - c * H96;
        Qs[c][pp] = qbase[(size_t)c * HW + pp];
        Ks[c][pp] = kbase[(size_t)c * HW + pp];
    }
    __syncthreads();
    const int ti = threadIdx.x & 15, tj = threadIdx.x >> 4;
    const int i0 = ti * 6, j0 = tj * 6;
    float acc[6][6];
#pragma unroll
    for (int i = 0; i < 6; i++)
#pragma unroll
        for (int j = 0; j < 6; j++) acc[i][j] = 0.f;

    for (int c = 0; c < C8C; c++) {
        float a[6], kb[6];
#pragma unroll
        for (int j = 0; j < 6; j++) { a[j] = Qs[c][i0 + j]; kb[j] = Ks[c][j0 + j]; }
#pragma unroll
        for (int i = 0; i < 6; i++)
#pragma unroll
            for (int j = 0; j < 6; j++) acc[i][j] += a[i] * kb[j];
    }
#pragma unroll
    for (int i = 0; i < 6; i++) {
        int qi = i0 + i;
        float* row;
        if (MASK) row = att + ((size_t)((b * H96 + qi) * H96 + s)) * ATT_N + j0;
        else      row = att + ((size_t)((b * H96 + s) * H96 + qi)) * ATT_N + H96 + j0;
#pragma unroll
        for (int j = 0; j < 6; j++) {
            float v = acc[i][j];
            if (MASK && qi == j0 + j) v = -1e30f;
            row[j] = v;
        }
    }
}

// ---------------- softmax ----------------
__global__ void softmax_kernel(float* __restrict__ att)
{
    const int gw   = (blockIdx.x * blockDim.x + threadIdx.x) >> 5;
    const int lane = threadIdx.x & 31;
    if (gw >= NB * HW) return;
    float* row = att + (size_t)gw * ATT_N;
    float v[6];
    float mx = -1e30f;
#pragma unroll
    for (int i = 0; i < 6; i++) { v[i] = row[lane + 32 * i]; mx = fmaxf(mx, v[i]); }
#pragma unroll
    for (int o = 16; o > 0; o >>= 1) mx = fmaxf(mx, __shfl_xor_sync(0xffffffffu, mx, o));
    float sum = 0.f;
#pragma unroll
    for (int i = 0; i < 6; i++) { v[i] = __expf(v[i] - mx); sum += v[i]; }
#pragma unroll
    for (int o = 16; o > 0; o >>= 1) sum += __shfl_xor_sync(0xffffffffu, sum, o);
    float inv = 1.f / sum;
#pragma unroll
    for (int i = 0; i < 6; i++) row[lane + 32 * i] = v[i] * inv;
}

// ---------------- attention apply ----------------
template<int MODE>
__global__ void __launch_bounds__(256) outgemm_kernel(
    const float* __restrict__ Vp, const float* __restrict__ att, float* __restrict__ O)
{
    const int bs = blockIdx.y;
    const int b  = bs / H96;
    const int s  = bs - b * H96;
    const int c0 = blockIdx.x * 128;
    __shared__ __align__(16) float Vs[16][132];
    __shared__ __align__(16) float Ash[16][100];
    const int tid = threadIdx.x;
    const int tm = tid >> 4, tn = tid & 15;
    u64 acc[8][3];
#pragma unroll
    for (int i = 0; i < 8; i++)
#pragma unroll
        for (int j = 0; j < 3; j++) acc[i][j] = 0ull;

    const float* vbase = Vp + ((size_t)(b * CIN + c0)) * HW + s * H96;

    for (int k0 = 0; k0 < H96; k0 += 16) {
#pragma unroll
        for (int i = 0; i < 8; i++) {
            int e = i * 256 + tid;
            int c = e >> 4, k = e & 15;
            Vs[k][c] = vbase[(size_t)c * HW + k0 + k];
        }
#pragma unroll
        for (int i = 0; i < 6; i++) {
            int e = i * 256 + tid;
            int r = e >> 4, k = e & 15;
            size_t aidx;
            if (MODE == 0) aidx = ((size_t)((b * H96 + r) * H96 + s)) * ATT_N + k0 + k;
            else           aidx = ((size_t)((b * H96 + s) * H96 + r)) * ATT_N + H96 + k0 + k;
            Ash[k][r] = att[aidx];
        }
        __syncthreads();
#pragma unroll
        for (int kk = 0; kk < 16; kk++) {
            const float4 a0 = *reinterpret_cast<const float4*>(&Vs[kk][tm * 8]);
            const float4 a1 = *reinterpret_cast<const float4*>(&Vs[kk][tm * 8 + 4]);
            u64 ap[8];
            ap[0] = pack2(a0.x); ap[1] = pack2(a0.y); ap[2] = pack2(a0.z); ap[3] = pack2(a0.w);
            ap[4] = pack2(a1.x); ap[5] = pack2(a1.y); ap[6] = pack2(a1.z); ap[7] = pack2(a1.w);
            const u64* bp64 = reinterpret_cast<const u64*>(&Ash[kk][tn * 6]);
            u64 bp[3] = { bp64[0], bp64[1], bp64[2] };
#pragma unroll
            for (int mi = 0; mi < 8; mi++)
#pragma unroll
                for (int nj = 0; nj < 3; nj++)
                    fma2(acc[mi][nj], ap[mi], bp[nj]);
        }
        __syncthreads();
    }

    float* obase = O + ((size_t)(b * CIN + c0)) * HW + s * H96;
#pragma unroll
    for (int mi = 0; mi < 8; mi++) {
        float* orow = obase + (size_t)(tm * 8 + mi) * HW + tn * 6;
        float2 p0 = unpack2(acc[mi][0]);
        float2 p1 = unpack2(acc[mi][1]);
        float2 p2 = unpack2(acc[mi][2]);
        orow[0] = p0.x; orow[1] = p0.y; orow[2] = p1.x;
        orow[3] = p1.y; orow[4] = p2.x; orow[5] = p2.y;
    }
}

// ---------------- final ----------------
__global__ void final_kernel(const float* __restrict__ OH, const float* __restrict__ OW,
                             const float* __restrict__ x, const float* __restrict__ gamma,
                             float* __restrict__ out)
{
    __shared__ float t[32][33];
    const int p  = blockIdx.z;
    const int h0 = blockIdx.y * 32, w0 = blockIdx.x * 32;
    const size_t base = (size_t)p * HW;
    const float g = gamma[0];
    for (int i = threadIdx.y; i < 32; i += 8)
        t[i][threadIdx.x] = OH[base + (size_t)(w0 + i) * H96 + h0 + threadIdx.x];
    __syncthreads();
    for (int i = threadIdx.y; i < 32; i += 8) {
        size_t idx = base + (size_t)(h0 + i) * H96 + w0 + threadIdx.x;
        out[idx] = g * (t[threadIdx.x][i] + OW[idx]) + x[idx];
    }
}

// ---------------- launch ----------------
extern "C" void kernel_launch(void* const* d_in, const int* in_sizes, int n_in,
                              void* d_out, int out_size)
{
    const float* x     = (const float*)d_in[0];
    const float* wqh   = (const float*)d_in[1];
    const float* bqh   = (const float*)d_in[2];
    const float* wqw   = (const float*)d_in[3];
    const float* bqw   = (const float*)d_in[4];
    const float* wkh   = (const float*)d_in[5];
    const float* bkh   = (const float*)d_in[6];
    const float* wkw   = (const float*)d_in[7];
    const float* bkw   = (const float*)d_in[8];
    const float* wvh   = (const float*)d_in[9];
    const float* bvh   = (const float*)d_in[10];
    const float* wvw   = (const float*)d_in[11];
    const float* bvw   = (const float*)d_in[12];
    const float* gamma = (const float*)d_in[13];
    float* out = (float*)d_out;

    float *wqkv, *wqkh, *wvv, *wvh2, *xt, *qh, *kh, *vh, *qw, *kw, *vw,
          *qhT, *khT, *vhT, *att, *oh, *ow;
    cudaGetSymbolAddress((void**)&wqkv, g_wqkv);
    cudaGetSymbolAddress((void**)&wqkh, g_wqkh);
    cudaGetSymbolAddress((void**)&wvv,  g_wvv);
    cudaGetSymbolAddress((void**)&wvh2, g_wvh2);
    cudaGetSymbolAddress((void**)&xt,   g_xt);
    cudaGetSymbolAddress((void**)&qh,  g_qh);
    cudaGetSymbolAddress((void**)&kh,  g_kh);
    cudaGetSymbolAddress((void**)&vh,  g_vh);
    cudaGetSymbolAddress((void**)&qw,  g_qw);
    cudaGetSymbolAddress((void**)&kw,  g_kw);
    cudaGetSymbolAddress((void**)&vw,  g_vw);
    cudaGetSymbolAddress((void**)&qhT, g_qhT);
    cudaGetSymbolAddress((void**)&khT, g_khT);
    cudaGetSymbolAddress((void**)&vhT, g_vhT);
    cudaGetSymbolAddress((void**)&att, g_att);
    cudaGetSymbolAddress((void**)&oh,  g_oh);
    cudaGetSymbolAddress((void**)&ow,  g_ow);

    // opt-in to >48KB dynamic smem for v_conv (host-side attr set; capture-safe)
    cudaFuncSetAttribute(v_conv<0>, cudaFuncAttributeMaxDynamicSharedMemorySize, VSMEM_BYTES);
    cudaFuncSetAttribute(v_conv<1>, cudaFuncAttributeMaxDynamicSharedMemorySize, VSMEM_BYTES);

    prep_qk<<<(KTOT * MQK + 255) / 256, 256>>>(wqh, wkh, wqkv);
    prep_qk<<<(KTOT * MQK + 255) / 256, 256>>>(wqw, wkw, wqkh);
    prep_v <<<(KTOT * VM  + 255) / 256, 256>>>(wvh, wvv);
    prep_v <<<(KTOT * VM  + 255) / 256, 256>>>(wvw, wvh2);
    prep_x <<<(NB * CIN * HW + 255) / 256, 256>>>(x, xt);

    qk_conv<0><<<dim3(72, 1, NB), 128>>>(x, wqkv, bqh, bkh, qh, kh);
    qk_conv<1><<<dim3(72, 1, NB), 128>>>(x, wqkh, bqw, bkw, qw, kw);
    v_conv<0><<<dim3(72, 2, NB), 256, VSMEM_BYTES>>>(xt, wvv,  bvh, vh);
    v_conv<1><<<dim3(72, 2, NB), 256, VSMEM_BYTES>>>(xt, wvh2, bvw, vw);

    transpose_hw<<<dim3(3, 3, NB * C8C), dim3(32, 8)>>>(qh, qhT);
    transpose_hw<<<dim3(3, 3, NB * C8C), dim3(32, 8)>>>(kh, khT);
    transpose_hw<<<dim3(3, 3, NB * CIN), dim3(32, 8)>>>(vh, vhT);

    logits_kernel<true ><<<NB * H96, 256>>>(qhT, khT, att);
    logits_kernel<false><<<NB * H96, 256>>>(qw,  kw,  att);

    softmax_kernel<<<(NB * HW) / 8, 256>>>(att);

    outgemm_kernel<0><<<dim3(2, NB * H96), 256>>>(vhT, att, oh);
    outgemm_kernel<1><<<dim3(2, NB * H96), 256>>>(vw,  att, ow);

    final_kernel<<<dim3(3, 3, NB * CIN), dim3(32, 8)>>>(oh, ow, x, gamma, out);
}